// round 9
// baseline (speedup 1.0000x reference)
#include <cuda_runtime.h>
#include <cuda_fp16.h>
#include <cstdint>

#define NN   50000
#define EE   800000
#define MT   391          // ceil(NN/128)
#define SB   98           // scan blocks (512 each)

// ---------------- scratch ----------------
__device__ int      g_cnt[NN];
__device__ int      g_off[NN + 1];
__device__ int      g_cur[NN];
__device__ int      g_csr[EE];
__device__ int      g_bsum[SB];
__device__ float    g_T0[NN * 128];           // ping-pong fp32 self halves
__device__ float    g_T1[NN * 128];
__device__ uint32_t g_Tn0[NN * 64];           // ping-pong half2 neighbor payloads
__device__ uint32_t g_Tn1[NN * 64];
__device__ uint32_t g_Ah[MT * 128 * 64];      // layer-0 input images (x)
__device__ uint32_t g_Al[MT * 128 * 64];
__device__ uint32_t g_Wh[2 * 16384 + 8192];   // weights bf16x2 [k2][n]
__device__ uint32_t g_Wl[2 * 16384 + 8192];

// ---------------- bf16 helpers ----------------
__device__ __forceinline__ uint32_t pack_bf2(float lo, float hi) {
    uint32_t r;
    asm("cvt.rn.bf16x2.f32 %0, %1, %2;" : "=r"(r) : "f"(hi), "f"(lo));
    return r;
}
__device__ __forceinline__ void split_pair(float a, float b, uint32_t& h, uint32_t& l) {
    h = pack_bf2(a, b);
    float ha = __uint_as_float(h << 16);
    float hb = __uint_as_float(h & 0xffff0000u);
    l = pack_bf2(a - ha, b - hb);
}
__device__ __forceinline__ void mma16(float* c, const uint32_t* a, const uint32_t* b) {
    asm volatile(
        "mma.sync.aligned.m16n8k16.row.col.f32.bf16.bf16.f32 "
        "{%0,%1,%2,%3}, {%4,%5,%6,%7}, {%8,%9}, {%0,%1,%2,%3};\n"
        : "+f"(c[0]), "+f"(c[1]), "+f"(c[2]), "+f"(c[3])
        : "r"(a[0]), "r"(a[1]), "r"(a[2]), "r"(a[3]), "r"(b[0]), "r"(b[1]));
}

// ---------------- fused prep ----------------
__global__ void k_prep(const float* __restrict__ x,
                       const float* __restrict__ Ws0, const float* __restrict__ Wn0,
                       const float* __restrict__ Ws1, const float* __restrict__ Wn1,
                       const float* __restrict__ Ws2, const float* __restrict__ Wn2) {
    int id = blockIdx.x * blockDim.x + threadIdx.x;
    if (id < NN) g_cnt[id] = 0;
    if (id < 40960) {
        int l, local, wbase, nw;
        if (id < 16384)      { l = 0; local = id;         wbase = 0;     nw = 256; }
        else if (id < 32768) { l = 1; local = id - 16384; wbase = 16384; nw = 256; }
        else                 { l = 2; local = id - 32768; wbase = 32768; nw = 128; }
        int k2 = local / nw, n = local % nw, k = k2 * 2, d = nw >> 1;
        float v0, v1;
        if (l == 0) {
            v0 = (n < d) ? Ws0[k * d + n] : Wn0[k * d + n - d];
            v1 = (n < d) ? Ws0[(k + 1) * d + n] : Wn0[(k + 1) * d + n - d];
        } else if (l == 1) {
            v0 = (n < d) ? Ws1[k * d + n] : Wn1[k * d + n - d];
            v1 = (n < d) ? Ws1[(k + 1) * d + n] : Wn1[(k + 1) * d + n - d];
        } else {
            v0 = (n < d) ? Ws2[k * d + n] : Wn2[k * d + n - d];
            v1 = (n < d) ? Ws2[(k + 1) * d + n] : Wn2[(k + 1) * d + n - d];
        }
        uint32_t h, lo;
        split_pair(v0, v1, h, lo);
        g_Wh[wbase + k2 * nw + n] = h;
        g_Wl[wbase + k2 * nw + n] = lo;
    }
    if (id < NN * 64) {
        int n = id >> 6, k2 = id & 63;
        float2 v = *reinterpret_cast<const float2*>(x + n * 128 + k2 * 2);
        uint32_t h, lo;
        split_pair(v.x, v.y, h, lo);
        g_Ah[n * 64 + k2] = h;
        g_Al[n * 64 + k2] = lo;
    }
}

// ---------------- CSR build ----------------
__global__ void k_hist(const int* __restrict__ dst) {
    int e = blockIdx.x * blockDim.x + threadIdx.x;
    if (e < EE) atomicAdd(&g_cnt[dst[e]], 1);
}
__global__ __launch_bounds__(512) void k_scanA() {
    __shared__ int ss[512];
    int t = threadIdx.x, i = blockIdx.x * 512 + t;
    ss[t] = (i < NN) ? g_cnt[i] : 0;
    __syncthreads();
    for (int d = 256; d > 0; d >>= 1) {
        if (t < d) ss[t] += ss[t + d];
        __syncthreads();
    }
    if (t == 0) g_bsum[blockIdx.x] = ss[0];
}
__global__ __launch_bounds__(512) void k_scanC() {
    __shared__ int bs[128];
    __shared__ int ss[512];
    int t = threadIdx.x, i = blockIdx.x * 512 + t;
    if (t < 128) bs[t] = (t < SB) ? g_bsum[t] : 0;
    int v0 = (i < NN) ? g_cnt[i] : 0;
    ss[t] = v0;
    __syncthreads();
    for (int d = 1; d < 128; d <<= 1) {
        int v = (t < 128 && t >= d) ? bs[t - d] : 0;
        __syncthreads();
        if (t < 128) bs[t] += v;
        __syncthreads();
    }
    for (int d = 1; d < 512; d <<= 1) {
        int v = (t >= d) ? ss[t - d] : 0;
        __syncthreads();
        ss[t] += v;
        __syncthreads();
    }
    if (i < NN) {
        int base = (blockIdx.x > 0) ? bs[blockIdx.x - 1] : 0;
        int off = base + ss[t] - v0;
        g_off[i] = off;
        g_cur[i] = off;
    }
    if (i == NN - 1) g_off[NN] = EE;
}
__global__ void k_scatter(const int* __restrict__ src, const int* __restrict__ dst) {
    int e = blockIdx.x * blockDim.x + threadIdx.x;
    if (e < EE) {
        int p = atomicAdd(&g_cur[dst[e]], 1);
        g_csr[p] = src[e];
    }
}

// ---------------- fused GEMM ----------------
// MODE 0: A from g_Ah/g_Al (layer 0). MODE 1: A = finish(prev layer) in prologue.
// rdsel picks the READ buffers; wrsel picks the WRITE buffers (ping-pong, no races).
template <int NC, int MODE>
__global__ __launch_bounds__(512) void k_gemmF(int wb, int dsplit, int tn_str,
                                               const float* __restrict__ bias,
                                               int rdsel, int wrsel) {
    constexpr int NT = NC / 32;
    constexpr int BP = NC + 8;
    constexpr int NB = NC / 128;
    constexpr int AP = 68;

    extern __shared__ uint32_t sm[];
    uint32_t (*As_h)[AP] = reinterpret_cast<uint32_t(*)[AP]>(sm);
    uint32_t (*As_l)[AP] = reinterpret_cast<uint32_t(*)[AP]>(sm + 128 * AP);
    uint32_t (*Bs_h)[BP] = reinterpret_cast<uint32_t(*)[BP]>(sm + 2 * 128 * AP);
    uint32_t (*Bs_l)[BP] = reinterpret_cast<uint32_t(*)[BP]>(sm + 2 * 128 * AP + 16 * BP);

    int tid  = threadIdx.x;
    int bm   = blockIdx.x * 128;
    int warp = tid >> 5, lane = tid & 31;
    int wm = (warp & 3) * 32;
    int wn = (warp >> 2) * (NC / 4);
    int gi = lane >> 2;
    int ti = lane & 3;

    const float*    rdT  = rdsel ? g_T1 : g_T0;
    const uint32_t* rdTn = rdsel ? g_Tn1 : g_Tn0;
    float*          wrT  = wrsel ? g_T1 : g_T0;
    uint32_t*       wrTn = wrsel ? g_Tn1 : g_Tn0;

    // ---- prologue: build A tile ----
    if (MODE == 0) {
        int row = tid >> 2, q = tid & 3;
        const uint4* GA_h = reinterpret_cast<const uint4*>(g_Ah + (bm + row) * 64);
        const uint4* GA_l = reinterpret_cast<const uint4*>(g_Al + (bm + row) * 64);
#pragma unroll
        for (int i = 0; i < 4; ++i) {
            *reinterpret_cast<uint4*>(&As_h[row][q * 16 + i * 4]) = GA_h[q * 4 + i];
            *reinterpret_cast<uint4*>(&As_l[row][q * 16 + i * 4]) = GA_l[q * 4 + i];
        }
    } else {
#pragma unroll
        for (int j = 0; j < 8; ++j) {
            int row = warp * 8 + j;
            int node = bm + row;
            float4 r = make_float4(0.f, 0.f, 0.f, 0.f);
            if (node < NN) {
                int s0 = g_off[node], s1 = g_off[node + 1];
                float inv = 1.0f / (float)((s1 - s0) > 0 ? (s1 - s0) : 1);
                float4 acc = make_float4(0.f, 0.f, 0.f, 0.f);
                for (int i = s0; i < s1; ++i) {
                    int s = g_csr[i];
                    uint2 v = *reinterpret_cast<const uint2*>(rdTn + s * 64 + lane * 2);
                    float2 a0 = __half22float2(*reinterpret_cast<__half2*>(&v.x));
                    float2 a1 = __half22float2(*reinterpret_cast<__half2*>(&v.y));
                    acc.x += a0.x; acc.y += a0.y; acc.z += a1.x; acc.w += a1.y;
                }
                float4 p = *reinterpret_cast<const float4*>(rdT + node * 128 + lane * 4);
                float4 b = *reinterpret_cast<const float4*>(bias + lane * 4);
                r.x = fmaxf(p.x + acc.x * inv + b.x, 0.f);
                r.y = fmaxf(p.y + acc.y * inv + b.y, 0.f);
                r.z = fmaxf(p.z + acc.z * inv + b.z, 0.f);
                r.w = fmaxf(p.w + acc.w * inv + b.w, 0.f);
            }
            uint32_t h0, l0, h1, l1;
            split_pair(r.x, r.y, h0, l0);
            split_pair(r.z, r.w, h1, l1);
            As_h[row][lane * 2] = h0;     As_l[row][lane * 2] = l0;
            As_h[row][lane * 2 + 1] = h1; As_l[row][lane * 2 + 1] = l1;
        }
    }
    __syncthreads();

    // ---- mainloop ----
    const uint4* GW_h = reinterpret_cast<const uint4*>(g_Wh);
    const uint4* GW_l = reinterpret_cast<const uint4*>(g_Wl);
    int wb4 = wb >> 2;

    float c[2][NT][4];
#pragma unroll
    for (int mt = 0; mt < 2; ++mt)
#pragma unroll
        for (int nt = 0; nt < NT; ++nt)
#pragma unroll
            for (int i = 0; i < 4; ++i) c[mt][nt][i] = 0.f;

    uint4 pBh[NB], pBl[NB];

#define PREF(kc)                                                                  \
    do {                                                                          \
        _Pragma("unroll")                                                         \
        for (int j = 0; j < NB; ++j) {                                            \
            int idx = tid + j * 512;                                              \
            int kr = idx / (NC / 4), c4 = idx % (NC / 4);                         \
            pBh[j] = GW_h[wb4 + (((kc) * 16 + kr) * NC >> 2) + c4];               \
            pBl[j] = GW_l[wb4 + (((kc) * 16 + kr) * NC >> 2) + c4];               \
        }                                                                         \
    } while (0)

    PREF(0);

    for (int kc = 0; kc < 4; ++kc) {
#pragma unroll
        for (int j = 0; j < NB; ++j) {
            int idx = tid + j * 512;
            int kr = idx / (NC / 4), c4 = idx % (NC / 4);
            *reinterpret_cast<uint4*>(&Bs_h[kr][c4 * 4]) = pBh[j];
            *reinterpret_cast<uint4*>(&Bs_l[kr][c4 * 4]) = pBl[j];
        }
        __syncthreads();

        if (kc < 3) PREF(kc + 1);

#pragma unroll
        for (int st = 0; st < 2; ++st) {
            int kb2 = kc * 16 + st * 8;
            int bb2 = st * 8;
            uint32_t ah[2][4], al[2][4];
#pragma unroll
            for (int mt = 0; mt < 2; ++mt) {
                int rb = wm + mt * 16 + gi;
                ah[mt][0] = As_h[rb][kb2 + ti];
                ah[mt][1] = As_h[rb + 8][kb2 + ti];
                ah[mt][2] = As_h[rb][kb2 + ti + 4];
                ah[mt][3] = As_h[rb + 8][kb2 + ti + 4];
                al[mt][0] = As_l[rb][kb2 + ti];
                al[mt][1] = As_l[rb + 8][kb2 + ti];
                al[mt][2] = As_l[rb][kb2 + ti + 4];
                al[mt][3] = As_l[rb + 8][kb2 + ti + 4];
            }
#pragma unroll
            for (int nt = 0; nt < NT; ++nt) {
                int cb = wn + nt * 8 + gi;
                uint32_t bh[2], bl[2];
                bh[0] = Bs_h[bb2 + ti][cb];
                bh[1] = Bs_h[bb2 + ti + 4][cb];
                bl[0] = Bs_l[bb2 + ti][cb];
                bl[1] = Bs_l[bb2 + ti + 4][cb];
#pragma unroll
                for (int mt = 0; mt < 2; ++mt) {
                    mma16(c[mt][nt], ah[mt], bh);
                    mma16(c[mt][nt], al[mt], bh);
                    mma16(c[mt][nt], ah[mt], bl);
                }
            }
        }
        __syncthreads();
    }
#undef PREF

    // ---- epilogue ----
#pragma unroll
    for (int mt = 0; mt < 2; ++mt) {
        int r0 = bm + wm + mt * 16 + gi;
        int r1 = r0 + 8;
#pragma unroll
        for (int nt = 0; nt < NT; ++nt) {
            int colg = wn + nt * 8 + ti * 2;
            if (colg < dsplit) {
                if (r0 < NN)
                    *reinterpret_cast<float2*>(wrT + r0 * dsplit + colg) =
                        make_float2(c[mt][nt][0], c[mt][nt][1]);
                if (r1 < NN)
                    *reinterpret_cast<float2*>(wrT + r1 * dsplit + colg) =
                        make_float2(c[mt][nt][2], c[mt][nt][3]);
            } else {
                int pc = (colg - dsplit) >> 1;
                if (r0 < NN) {
                    __half2 h2 = __floats2half2_rn(c[mt][nt][0], c[mt][nt][1]);
                    wrTn[r0 * tn_str + pc] = *reinterpret_cast<uint32_t*>(&h2);
                }
                if (r1 < NN) {
                    __half2 h2 = __floats2half2_rn(c[mt][nt][2], c[mt][nt][3]);
                    wrTn[r1 * tn_str + pc] = *reinterpret_cast<uint32_t*>(&h2);
                }
            }
        }
    }
}

// ---------------- final finish (layer 2 output, d=64; reads buffer 0) --------
__global__ __launch_bounds__(256) void k_finish2(const float* __restrict__ bias,
                                                 float* __restrict__ outext) {
    int warp = threadIdx.x >> 5, lane = threadIdx.x & 31;
    int n = blockIdx.x * 8 + warp;
    if (n >= NN) return;
    int s0 = g_off[n], s1 = g_off[n + 1];
    float inv = 1.0f / (float)((s1 - s0) > 0 ? (s1 - s0) : 1);
    float2 acc = make_float2(0.f, 0.f);
    float2 ac2 = make_float2(0.f, 0.f);
    int i = s0;
    for (; i + 2 <= s1; i += 2) {
        uint32_t va = g_Tn0[g_csr[i] * 32 + lane];
        uint32_t vb = g_Tn0[g_csr[i + 1] * 32 + lane];
        float2 a = __half22float2(*reinterpret_cast<__half2*>(&va));
        float2 b = __half22float2(*reinterpret_cast<__half2*>(&vb));
        acc.x += a.x; acc.y += a.y;
        ac2.x += b.x; ac2.y += b.y;
    }
    if (i < s1) {
        uint32_t va = g_Tn0[g_csr[i] * 32 + lane];
        float2 a = __half22float2(*reinterpret_cast<__half2*>(&va));
        acc.x += a.x; acc.y += a.y;
    }
    acc.x += ac2.x; acc.y += ac2.y;
    float2 p = *reinterpret_cast<const float2*>(g_T0 + n * 64 + lane * 2);
    float2 b = *reinterpret_cast<const float2*>(bias + lane * 2);
    float2 r;
    r.x = p.x + acc.x * inv + b.x;
    r.y = p.y + acc.y * inv + b.y;
    *reinterpret_cast<float2*>(outext + n * 64 + lane * 2) = r;
}

// ---------------- launch ----------------
extern "C" void kernel_launch(void* const* d_in, const int* in_sizes, int n_in,
                              void* d_out, int out_size) {
    const float* x   = (const float*)d_in[0];
    const int*   src = (const int*)d_in[1];
    const int*   dst = (const int*)d_in[2];
    const float* Ws0 = (const float*)d_in[3];
    const float* Wn0 = (const float*)d_in[4];
    const float* b0  = (const float*)d_in[5];
    const float* Ws1 = (const float*)d_in[6];
    const float* Wn1 = (const float*)d_in[7];
    const float* b1  = (const float*)d_in[8];
    const float* Ws2 = (const float*)d_in[9];
    const float* Wn2 = (const float*)d_in[10];
    const float* b2  = (const float*)d_in[11];
    float* out = (float*)d_out;

    const int SM256 = 69632 + 2 * 16 * 264 * 4;   // 103424
    const int SM128 = 69632 + 2 * 16 * 136 * 4;   // 87040
    cudaFuncSetAttribute(k_gemmF<256, 0>, cudaFuncAttributeMaxDynamicSharedMemorySize, SM256);
    cudaFuncSetAttribute(k_gemmF<256, 1>, cudaFuncAttributeMaxDynamicSharedMemorySize, SM256);
    cudaFuncSetAttribute(k_gemmF<128, 1>, cudaFuncAttributeMaxDynamicSharedMemorySize, SM128);

    k_prep<<<(NN * 64 + 255) / 256, 256>>>(x, Ws0, Wn0, Ws1, Wn1, Ws2, Wn2);
    k_hist<<<(EE + 255) / 256, 256>>>(dst);
    k_scanA<<<SB, 512>>>();
    k_scanC<<<SB, 512>>>();
    k_scatter<<<(EE + 255) / 256, 256>>>(src, dst);

    // Layer 0: A from x images -> write buffers 0
    k_gemmF<256, 0><<<MT, 512, SM256>>>(0, 128, 64, nullptr, 0, 0);
    // Layer 1: finish(b0) from buffers 0 -> write buffers 1
    k_gemmF<256, 1><<<MT, 512, SM256>>>(16384, 128, 64, b0, 0, 1);
    // Layer 2: finish(b1) from buffers 1 -> write buffers 0
    k_gemmF<128, 1><<<MT, 512, SM128>>>(32768, 64, 32, b1, 1, 0);
    // Final: out = T_self + mean + b2 (buffers 0)
    k_finish2<<<(NN + 7) / 8, 256>>>(b2, out);
}

// round 10
// speedup vs baseline: 1.0635x; 1.0635x over previous
#include <cuda_runtime.h>
#include <cuda_fp16.h>
#include <cstdint>

#define NN   50000
#define EE   800000
#define MT   391          // ceil(NN/128)
#define SB   98           // scan blocks (512 each)

// ---------------- scratch ----------------
__device__ int      g_cnt[NN];
__device__ int      g_off[NN + 1];
__device__ int      g_cur[NN];
__device__ int      g_csr[EE];
__device__ int      g_bsum[SB];
__device__ float    g_T[NN * 128];            // fp32 self half
__device__ uint32_t g_Tn[NN * 64];            // half2 neighbor payload
__device__ uint32_t g_Ah[MT * 128 * 64];      // activation images bf16x2-hi [row][k2]
__device__ uint32_t g_Al[MT * 128 * 64];
__device__ uint32_t g_Wh[2 * 16384 + 8192];   // weights bf16x2 [k2][n]
__device__ uint32_t g_Wl[2 * 16384 + 8192];

// ---------------- bf16 helpers ----------------
__device__ __forceinline__ uint32_t pack_bf2(float lo, float hi) {
    uint32_t r;
    asm("cvt.rn.bf16x2.f32 %0, %1, %2;" : "=r"(r) : "f"(hi), "f"(lo));
    return r;
}
__device__ __forceinline__ void split_pair(float a, float b, uint32_t& h, uint32_t& l) {
    h = pack_bf2(a, b);
    float ha = __uint_as_float(h << 16);
    float hb = __uint_as_float(h & 0xffff0000u);
    l = pack_bf2(a - ha, b - hb);
}
__device__ __forceinline__ void mma16(float* c, const uint32_t* a, const uint32_t* b) {
    asm volatile(
        "mma.sync.aligned.m16n8k16.row.col.f32.bf16.bf16.f32 "
        "{%0,%1,%2,%3}, {%4,%5,%6,%7}, {%8,%9}, {%0,%1,%2,%3};\n"
        : "+f"(c[0]), "+f"(c[1]), "+f"(c[2]), "+f"(c[3])
        : "r"(a[0]), "r"(a[1]), "r"(a[2]), "r"(a[3]), "r"(b[0]), "r"(b[1]));
}

// ---------------- fused prep: zero counts + weight/x conversion ----------------
__global__ void k_prep(const float* __restrict__ x,
                       const float* __restrict__ Ws0, const float* __restrict__ Wn0,
                       const float* __restrict__ Ws1, const float* __restrict__ Wn1,
                       const float* __restrict__ Ws2, const float* __restrict__ Wn2) {
    int id = blockIdx.x * blockDim.x + threadIdx.x;
    if (id < NN) g_cnt[id] = 0;
    if (id < 40960) {
        int l, local, wbase, nw;
        if (id < 16384)      { l = 0; local = id;         wbase = 0;     nw = 256; }
        else if (id < 32768) { l = 1; local = id - 16384; wbase = 16384; nw = 256; }
        else                 { l = 2; local = id - 32768; wbase = 32768; nw = 128; }
        int k2 = local / nw, n = local % nw, k = k2 * 2, d = nw >> 1;
        float v0, v1;
        if (l == 0) {
            v0 = (n < d) ? Ws0[k * d + n] : Wn0[k * d + n - d];
            v1 = (n < d) ? Ws0[(k + 1) * d + n] : Wn0[(k + 1) * d + n - d];
        } else if (l == 1) {
            v0 = (n < d) ? Ws1[k * d + n] : Wn1[k * d + n - d];
            v1 = (n < d) ? Ws1[(k + 1) * d + n] : Wn1[(k + 1) * d + n - d];
        } else {
            v0 = (n < d) ? Ws2[k * d + n] : Wn2[k * d + n - d];
            v1 = (n < d) ? Ws2[(k + 1) * d + n] : Wn2[(k + 1) * d + n - d];
        }
        uint32_t h, lo;
        split_pair(v0, v1, h, lo);
        g_Wh[wbase + k2 * nw + n] = h;
        g_Wl[wbase + k2 * nw + n] = lo;
    }
    if (id < NN * 64) {
        int n = id >> 6, k2 = id & 63;
        float2 v = *reinterpret_cast<const float2*>(x + n * 128 + k2 * 2);
        uint32_t h, lo;
        split_pair(v.x, v.y, h, lo);
        g_Ah[n * 64 + k2] = h;
        g_Al[n * 64 + k2] = lo;
    }
}

// ---------------- CSR build ----------------
__global__ void k_hist(const int* __restrict__ dst) {
    int e = blockIdx.x * blockDim.x + threadIdx.x;
    if (e < EE) atomicAdd(&g_cnt[dst[e]], 1);
}
__global__ __launch_bounds__(512) void k_scanA() {
    __shared__ int ss[512];
    int t = threadIdx.x, i = blockIdx.x * 512 + t;
    ss[t] = (i < NN) ? g_cnt[i] : 0;
    __syncthreads();
    for (int d = 256; d > 0; d >>= 1) {
        if (t < d) ss[t] += ss[t + d];
        __syncthreads();
    }
    if (t == 0) g_bsum[blockIdx.x] = ss[0];
}
// scanC: fused block-sum scan (redundant per block) + in-block scan
__global__ __launch_bounds__(512) void k_scanC() {
    __shared__ int bs[128];
    __shared__ int ss[512];
    int t = threadIdx.x, i = blockIdx.x * 512 + t;
    if (t < 128) bs[t] = (t < SB) ? g_bsum[t] : 0;
    int v0 = (i < NN) ? g_cnt[i] : 0;
    ss[t] = v0;
    __syncthreads();
    for (int d = 1; d < 128; d <<= 1) {
        int v = (t < 128 && t >= d) ? bs[t - d] : 0;
        __syncthreads();
        if (t < 128) bs[t] += v;
        __syncthreads();
    }
    for (int d = 1; d < 512; d <<= 1) {
        int v = (t >= d) ? ss[t - d] : 0;
        __syncthreads();
        ss[t] += v;
        __syncthreads();
    }
    if (i < NN) {
        int base = (blockIdx.x > 0) ? bs[blockIdx.x - 1] : 0;
        int off = base + ss[t] - v0;
        g_off[i] = off;
        g_cur[i] = off;
    }
    if (i == NN - 1) g_off[NN] = EE;
}
__global__ void k_scatter(const int* __restrict__ src, const int* __restrict__ dst) {
    int e = blockIdx.x * blockDim.x + threadIdx.x;
    if (e < EE) {
        int p = atomicAdd(&g_cur[dst[e]], 1);
        g_csr[p] = src[e];
    }
}

// ---------------- GEMM: 128 x NC tile, 512 threads, interleaved hi/lo smem ----
// 16 warps = 4(M) x 4(N); warp tile 32 x NC/4 = 2 mt x (NC/32) nt.
// smem: uint2 {hi, lo} so each fragment element is ONE LDS.64.
template <int NC>
__global__ __launch_bounds__(512) void k_gemm(int wb, int dsplit, int tn_str) {
    constexpr int NT  = NC / 32;
    constexpr int BP2 = NC + 4;           // Bs2 row stride (uint2): 2*BP2 ≡ 8 mod 32
    constexpr int NB  = NC / 128;

    extern __shared__ uint2 sm2[];
    uint2 (*As2)[20]  = reinterpret_cast<uint2(*)[20]>(sm2);           // stride 40w ≡ 8 mod 32
    uint2 (*Bs2)[BP2] = reinterpret_cast<uint2(*)[BP2]>(sm2 + 128 * 20);

    int tid  = threadIdx.x;
    int bm   = blockIdx.x * 128;
    int warp = tid >> 5, lane = tid & 31;
    int wm = (warp & 3) * 32;
    int wn = (warp >> 2) * (NC / 4);
    int gi = lane >> 2;
    int ti = lane & 3;

    const uint4* GA_h = reinterpret_cast<const uint4*>(g_Ah);
    const uint4* GA_l = reinterpret_cast<const uint4*>(g_Al);
    const uint4* GW_h = reinterpret_cast<const uint4*>(g_Wh);
    const uint4* GW_l = reinterpret_cast<const uint4*>(g_Wl);
    int wb4 = wb >> 2;

    int a_row = tid >> 2, a_q = tid & 3;

    float c[2][NT][4];
#pragma unroll
    for (int mt = 0; mt < 2; ++mt)
#pragma unroll
        for (int nt = 0; nt < NT; ++nt)
#pragma unroll
            for (int i = 0; i < 4; ++i) c[mt][nt][i] = 0.f;

    uint4 pAh, pAl, pBh[NB], pBl[NB];

#define PREF(kc)                                                                  \
    do {                                                                          \
        pAh = GA_h[(bm + a_row) * 16 + (kc) * 4 + a_q];                           \
        pAl = GA_l[(bm + a_row) * 16 + (kc) * 4 + a_q];                           \
        _Pragma("unroll")                                                         \
        for (int j = 0; j < NB; ++j) {                                            \
            int idx = tid + j * 512;                                              \
            int kr = idx / (NC / 4), c4 = idx % (NC / 4);                         \
            pBh[j] = GW_h[wb4 + (((kc) * 16 + kr) * NC >> 2) + c4];               \
            pBl[j] = GW_l[wb4 + (((kc) * 16 + kr) * NC >> 2) + c4];               \
        }                                                                         \
    } while (0)

    PREF(0);

    for (int kc = 0; kc < 4; ++kc) {
        // stage A chunk (interleaved)
        As2[a_row][a_q * 4 + 0] = make_uint2(pAh.x, pAl.x);
        As2[a_row][a_q * 4 + 1] = make_uint2(pAh.y, pAl.y);
        As2[a_row][a_q * 4 + 2] = make_uint2(pAh.z, pAl.z);
        As2[a_row][a_q * 4 + 3] = make_uint2(pAh.w, pAl.w);
        // stage B chunk (interleaved)
#pragma unroll
        for (int j = 0; j < NB; ++j) {
            int idx = tid + j * 512;
            int kr = idx / (NC / 4), c4 = idx % (NC / 4);
            Bs2[kr][c4 * 4 + 0] = make_uint2(pBh[j].x, pBl[j].x);
            Bs2[kr][c4 * 4 + 1] = make_uint2(pBh[j].y, pBl[j].y);
            Bs2[kr][c4 * 4 + 2] = make_uint2(pBh[j].z, pBl[j].z);
            Bs2[kr][c4 * 4 + 3] = make_uint2(pBh[j].w, pBl[j].w);
        }
        __syncthreads();

        if (kc < 3) PREF(kc + 1);

#pragma unroll
        for (int st = 0; st < 2; ++st) {
            int kb2 = st * 8;
            uint32_t ah[2][4], al[2][4];
#pragma unroll
            for (int mt = 0; mt < 2; ++mt) {
                int rb = wm + mt * 16 + gi;
                uint2 v0 = As2[rb][kb2 + ti];
                uint2 v1 = As2[rb + 8][kb2 + ti];
                uint2 v2 = As2[rb][kb2 + ti + 4];
                uint2 v3 = As2[rb + 8][kb2 + ti + 4];
                ah[mt][0] = v0.x; al[mt][0] = v0.y;
                ah[mt][1] = v1.x; al[mt][1] = v1.y;
                ah[mt][2] = v2.x; al[mt][2] = v2.y;
                ah[mt][3] = v3.x; al[mt][3] = v3.y;
            }
#pragma unroll
            for (int nt = 0; nt < NT; ++nt) {
                int cb = wn + nt * 8 + gi;
                uint2 w0 = Bs2[kb2 + ti][cb];
                uint2 w1 = Bs2[kb2 + ti + 4][cb];
                uint32_t bh[2] = { w0.x, w1.x };
                uint32_t bl[2] = { w0.y, w1.y };
#pragma unroll
                for (int mt = 0; mt < 2; ++mt) {
                    mma16(c[mt][nt], ah[mt], bh);
                    mma16(c[mt][nt], al[mt], bh);
                    mma16(c[mt][nt], ah[mt], bl);
                }
            }
        }
        __syncthreads();
    }
#undef PREF

    // epilogue: self cols -> fp32 g_T; neighbor cols -> half2 g_Tn
#pragma unroll
    for (int mt = 0; mt < 2; ++mt) {
        int r0 = bm + wm + mt * 16 + gi;
        int r1 = r0 + 8;
#pragma unroll
        for (int nt = 0; nt < NT; ++nt) {
            int colg = wn + nt * 8 + ti * 2;
            if (colg < dsplit) {
                if (r0 < NN)
                    *reinterpret_cast<float2*>(g_T + r0 * dsplit + colg) =
                        make_float2(c[mt][nt][0], c[mt][nt][1]);
                if (r1 < NN)
                    *reinterpret_cast<float2*>(g_T + r1 * dsplit + colg) =
                        make_float2(c[mt][nt][2], c[mt][nt][3]);
            } else {
                int pc = (colg - dsplit) >> 1;
                if (r0 < NN) {
                    __half2 h2 = __floats2half2_rn(c[mt][nt][0], c[mt][nt][1]);
                    g_Tn[r0 * tn_str + pc] = *reinterpret_cast<uint32_t*>(&h2);
                }
                if (r1 < NN) {
                    __half2 h2 = __floats2half2_rn(c[mt][nt][2], c[mt][nt][3]);
                    g_Tn[r1 * tn_str + pc] = *reinterpret_cast<uint32_t*>(&h2);
                }
            }
        }
    }
}

// ---------------- finish ----------------
// mode 0: h = relu(T_self + mean + b) -> write bf16 hi/lo images (next layer)
// mode 2: out = T_self + mean + b (d=64)
__global__ __launch_bounds__(256) void k_finish(const float* __restrict__ bias,
                                                float* __restrict__ outext, int mode) {
    int warp = threadIdx.x >> 5, lane = threadIdx.x & 31;
    int n = blockIdx.x * 8 + warp;
    if (n >= NN) return;
    int s0 = g_off[n], s1 = g_off[n + 1];
    float inv = 1.0f / (float)((s1 - s0) > 0 ? (s1 - s0) : 1);

    if (mode == 0) {
        float4 acc = make_float4(0.f, 0.f, 0.f, 0.f);
        float4 ac2 = make_float4(0.f, 0.f, 0.f, 0.f);
        int i = s0;
        for (; i + 2 <= s1; i += 2) {
            int sa = g_csr[i], sb = g_csr[i + 1];
            uint2 va = *reinterpret_cast<const uint2*>(g_Tn + sa * 64 + lane * 2);
            uint2 vb = *reinterpret_cast<const uint2*>(g_Tn + sb * 64 + lane * 2);
            float2 a0 = __half22float2(*reinterpret_cast<__half2*>(&va.x));
            float2 a1 = __half22float2(*reinterpret_cast<__half2*>(&va.y));
            float2 b0 = __half22float2(*reinterpret_cast<__half2*>(&vb.x));
            float2 b1 = __half22float2(*reinterpret_cast<__half2*>(&vb.y));
            acc.x += a0.x; acc.y += a0.y; acc.z += a1.x; acc.w += a1.y;
            ac2.x += b0.x; ac2.y += b0.y; ac2.z += b1.x; ac2.w += b1.y;
        }
        if (i < s1) {
            uint2 va = *reinterpret_cast<const uint2*>(g_Tn + g_csr[i] * 64 + lane * 2);
            float2 a0 = __half22float2(*reinterpret_cast<__half2*>(&va.x));
            float2 a1 = __half22float2(*reinterpret_cast<__half2*>(&va.y));
            acc.x += a0.x; acc.y += a0.y; acc.z += a1.x; acc.w += a1.y;
        }
        acc.x += ac2.x; acc.y += ac2.y; acc.z += ac2.z; acc.w += ac2.w;
        float4 p = *reinterpret_cast<const float4*>(g_T + n * 128 + lane * 4);
        float4 b = *reinterpret_cast<const float4*>(bias + lane * 4);
        float4 r;
        r.x = fmaxf(p.x + acc.x * inv + b.x, 0.f);
        r.y = fmaxf(p.y + acc.y * inv + b.y, 0.f);
        r.z = fmaxf(p.z + acc.z * inv + b.z, 0.f);
        r.w = fmaxf(p.w + acc.w * inv + b.w, 0.f);
        uint32_t h0, l0, h1, l1;
        split_pair(r.x, r.y, h0, l0);
        split_pair(r.z, r.w, h1, l1);
        int i0 = n * 64 + lane * 2;
        g_Ah[i0] = h0;     g_Al[i0] = l0;
        g_Ah[i0 + 1] = h1; g_Al[i0 + 1] = l1;
    } else {
        float2 acc = make_float2(0.f, 0.f);
        float2 ac2 = make_float2(0.f, 0.f);
        int i = s0;
        for (; i + 2 <= s1; i += 2) {
            uint32_t va = g_Tn[g_csr[i] * 32 + lane];
            uint32_t vb = g_Tn[g_csr[i + 1] * 32 + lane];
            float2 a = __half22float2(*reinterpret_cast<__half2*>(&va));
            float2 b = __half22float2(*reinterpret_cast<__half2*>(&vb));
            acc.x += a.x; acc.y += a.y;
            ac2.x += b.x; ac2.y += b.y;
        }
        if (i < s1) {
            uint32_t va = g_Tn[g_csr[i] * 32 + lane];
            float2 a = __half22float2(*reinterpret_cast<__half2*>(&va));
            acc.x += a.x; acc.y += a.y;
        }
        acc.x += ac2.x; acc.y += ac2.y;
        float2 p = *reinterpret_cast<const float2*>(g_T + n * 64 + lane * 2);
        float2 b = *reinterpret_cast<const float2*>(bias + lane * 2);
        float2 r;
        r.x = p.x + acc.x * inv + b.x;
        r.y = p.y + acc.y * inv + b.y;
        *reinterpret_cast<float2*>(outext + n * 64 + lane * 2) = r;
    }
}

// ---------------- launch ----------------
extern "C" void kernel_launch(void* const* d_in, const int* in_sizes, int n_in,
                              void* d_out, int out_size) {
    const float* x   = (const float*)d_in[0];
    const int*   src = (const int*)d_in[1];
    const int*   dst = (const int*)d_in[2];
    const float* Ws0 = (const float*)d_in[3];
    const float* Wn0 = (const float*)d_in[4];
    const float* b0  = (const float*)d_in[5];
    const float* Ws1 = (const float*)d_in[6];
    const float* Wn1 = (const float*)d_in[7];
    const float* b1  = (const float*)d_in[8];
    const float* Ws2 = (const float*)d_in[9];
    const float* Wn2 = (const float*)d_in[10];
    const float* b2  = (const float*)d_in[11];
    float* out = (float*)d_out;

    // dynamic smem: As2 (128*20*8 = 20480) + Bs2 (16*(NC+4)*8)
    const int SM256 = 20480 + 16 * 260 * 8;   // 53760
    const int SM128 = 20480 + 16 * 132 * 8;   // 37376
    cudaFuncSetAttribute(k_gemm<256>, cudaFuncAttributeMaxDynamicSharedMemorySize, SM256);
    cudaFuncSetAttribute(k_gemm<128>, cudaFuncAttributeMaxDynamicSharedMemorySize, SM128);

    k_prep<<<(NN * 64 + 255) / 256, 256>>>(x, Ws0, Wn0, Ws1, Wn1, Ws2, Wn2);
    k_hist<<<(EE + 255) / 256, 256>>>(dst);
    k_scanA<<<SB, 512>>>();
    k_scanC<<<SB, 512>>>();
    k_scatter<<<(EE + 255) / 256, 256>>>(src, dst);

    const int FB = (NN + 7) / 8;

    // Layer 0
    k_gemm<256><<<MT, 512, SM256>>>(0, 128, 64);
    k_finish<<<FB, 256>>>(b0, nullptr, 0);
    // Layer 1
    k_gemm<256><<<MT, 512, SM256>>>(16384, 128, 64);
    k_finish<<<FB, 256>>>(b1, nullptr, 0);
    // Layer 2
    k_gemm<128><<<MT, 512, SM128>>>(32768, 64, 32);
    k_finish<<<FB, 256>>>(b2, out, 2);
}

// round 11
// speedup vs baseline: 1.2735x; 1.1974x over previous
#include <cuda_runtime.h>
#include <cuda_fp16.h>
#include <cstdint>

#define NN   50000
#define EE   800000
#define MT   391          // ceil(NN/128)
#define SB   98           // scan blocks (512 each)

// ---------------- scratch ----------------
__device__ int      g_cnt[NN];
__device__ int      g_off[NN + 1];
__device__ int      g_cur[NN];
__device__ int      g_csr[EE];
__device__ int      g_bsum[SB];
__device__ float    g_T[NN * 128];            // fp32 self half
__device__ uint32_t g_Tn[NN * 64];            // half2 neighbor payload
__device__ uint32_t g_Ah[MT * 128 * 64];      // activation images bf16x2-hi [row][k2]
__device__ uint32_t g_Al[MT * 128 * 64];
__device__ uint32_t g_Wh[2 * 16384 + 8192];   // weights bf16x2 [k2][n]
__device__ uint32_t g_Wl[2 * 16384 + 8192];

// ---------------- bf16 helpers ----------------
__device__ __forceinline__ uint32_t pack_bf2(float lo, float hi) {
    uint32_t r;
    asm("cvt.rn.bf16x2.f32 %0, %1, %2;" : "=r"(r) : "f"(hi), "f"(lo));
    return r;
}
__device__ __forceinline__ void split_pair(float a, float b, uint32_t& h, uint32_t& l) {
    h = pack_bf2(a, b);
    float ha = __uint_as_float(h << 16);
    float hb = __uint_as_float(h & 0xffff0000u);
    l = pack_bf2(a - ha, b - hb);
}
__device__ __forceinline__ void mma16(float* c, const uint32_t* a, const uint32_t* b) {
    asm volatile(
        "mma.sync.aligned.m16n8k16.row.col.f32.bf16.bf16.f32 "
        "{%0,%1,%2,%3}, {%4,%5,%6,%7}, {%8,%9}, {%0,%1,%2,%3};\n"
        : "+f"(c[0]), "+f"(c[1]), "+f"(c[2]), "+f"(c[3])
        : "r"(a[0]), "r"(a[1]), "r"(a[2]), "r"(a[3]), "r"(b[0]), "r"(b[1]));
}

// ---------------- prep: weight/x conversion (no count zeroing here) ----------
__global__ void k_prep(const float* __restrict__ x,
                       const float* __restrict__ Ws0, const float* __restrict__ Wn0,
                       const float* __restrict__ Ws1, const float* __restrict__ Wn1,
                       const float* __restrict__ Ws2, const float* __restrict__ Wn2) {
    int id = blockIdx.x * blockDim.x + threadIdx.x;
    if (id < 40960) {
        int l, local, wbase, nw;
        if (id < 16384)      { l = 0; local = id;         wbase = 0;     nw = 256; }
        else if (id < 32768) { l = 1; local = id - 16384; wbase = 16384; nw = 256; }
        else                 { l = 2; local = id - 32768; wbase = 32768; nw = 128; }
        int k2 = local / nw, n = local % nw, k = k2 * 2, d = nw >> 1;
        float v0, v1;
        if (l == 0) {
            v0 = (n < d) ? Ws0[k * d + n] : Wn0[k * d + n - d];
            v1 = (n < d) ? Ws0[(k + 1) * d + n] : Wn0[(k + 1) * d + n - d];
        } else if (l == 1) {
            v0 = (n < d) ? Ws1[k * d + n] : Wn1[k * d + n - d];
            v1 = (n < d) ? Ws1[(k + 1) * d + n] : Wn1[(k + 1) * d + n - d];
        } else {
            v0 = (n < d) ? Ws2[k * d + n] : Wn2[k * d + n - d];
            v1 = (n < d) ? Ws2[(k + 1) * d + n] : Wn2[(k + 1) * d + n - d];
        }
        uint32_t h, lo;
        split_pair(v0, v1, h, lo);
        g_Wh[wbase + k2 * nw + n] = h;
        g_Wl[wbase + k2 * nw + n] = lo;
    }
    if (id < NN * 64) {
        int n = id >> 6, k2 = id & 63;
        float2 v = *reinterpret_cast<const float2*>(x + n * 128 + k2 * 2);
        uint32_t h, lo;
        split_pair(v.x, v.y, h, lo);
        g_Ah[n * 64 + k2] = h;
        g_Al[n * 64 + k2] = lo;
    }
}

// ---------------- CSR build (side stream) ----------------
__global__ void k_zero() {
    int i = blockIdx.x * blockDim.x + threadIdx.x;
    if (i < NN) g_cnt[i] = 0;
}
__global__ void k_hist(const int* __restrict__ dst) {
    int e = blockIdx.x * blockDim.x + threadIdx.x;
    if (e < EE) atomicAdd(&g_cnt[dst[e]], 1);
}
__global__ __launch_bounds__(512) void k_scanA() {
    __shared__ int ss[512];
    int t = threadIdx.x, i = blockIdx.x * 512 + t;
    ss[t] = (i < NN) ? g_cnt[i] : 0;
    __syncthreads();
    for (int d = 256; d > 0; d >>= 1) {
        if (t < d) ss[t] += ss[t + d];
        __syncthreads();
    }
    if (t == 0) g_bsum[blockIdx.x] = ss[0];
}
// fused: block-sum scan (redundant per block) + in-block scan
__global__ __launch_bounds__(512) void k_scanC() {
    __shared__ int bs[128];
    __shared__ int ss[512];
    int t = threadIdx.x, i = blockIdx.x * 512 + t;
    if (t < 128) bs[t] = (t < SB) ? g_bsum[t] : 0;
    int v0 = (i < NN) ? g_cnt[i] : 0;
    ss[t] = v0;
    __syncthreads();
    for (int d = 1; d < 128; d <<= 1) {
        int v = (t < 128 && t >= d) ? bs[t - d] : 0;
        __syncthreads();
        if (t < 128) bs[t] += v;
        __syncthreads();
    }
    for (int d = 1; d < 512; d <<= 1) {
        int v = (t >= d) ? ss[t - d] : 0;
        __syncthreads();
        ss[t] += v;
        __syncthreads();
    }
    if (i < NN) {
        int base = (blockIdx.x > 0) ? bs[blockIdx.x - 1] : 0;
        int off = base + ss[t] - v0;
        g_off[i] = off;
        g_cur[i] = off;
    }
    if (i == NN - 1) g_off[NN] = EE;
}
__global__ void k_scatter(const int* __restrict__ src, const int* __restrict__ dst) {
    int e = blockIdx.x * blockDim.x + threadIdx.x;
    if (e < EE) {
        int p = atomicAdd(&g_cur[dst[e]], 1);
        g_csr[p] = src[e];
    }
}

// ---------------- GEMM: 128 x NC tile, 512 threads (R7-proven layout) --------
// 16 warps = 4(M) x 4(N); warp tile 32 x NC/4 = 2 mt x (NC/32) nt.
template <int NC>
__global__ __launch_bounds__(512) void k_gemm(int wb, int dsplit, int tn_str) {
    constexpr int NT = NC / 32;
    constexpr int BP = NC + 8;
    constexpr int NB = NC / 128;

    extern __shared__ uint32_t sm[];
    uint32_t (*As_h)[20] = reinterpret_cast<uint32_t(*)[20]>(sm);
    uint32_t (*As_l)[20] = reinterpret_cast<uint32_t(*)[20]>(sm + 2560);
    uint32_t (*Bs_h)[BP] = reinterpret_cast<uint32_t(*)[BP]>(sm + 5120);
    uint32_t (*Bs_l)[BP] = reinterpret_cast<uint32_t(*)[BP]>(sm + 5120 + 16 * BP);

    int tid  = threadIdx.x;
    int bm   = blockIdx.x * 128;
    int warp = tid >> 5, lane = tid & 31;
    int wm = (warp & 3) * 32;
    int wn = (warp >> 2) * (NC / 4);
    int gi = lane >> 2;
    int ti = lane & 3;

    const uint4* GA_h = reinterpret_cast<const uint4*>(g_Ah);
    const uint4* GA_l = reinterpret_cast<const uint4*>(g_Al);
    const uint4* GW_h = reinterpret_cast<const uint4*>(g_Wh);
    const uint4* GW_l = reinterpret_cast<const uint4*>(g_Wl);
    int wb4 = wb >> 2;

    int a_row = tid >> 2, a_q = tid & 3;

    float c[2][NT][4];
#pragma unroll
    for (int mt = 0; mt < 2; ++mt)
#pragma unroll
        for (int nt = 0; nt < NT; ++nt)
#pragma unroll
            for (int i = 0; i < 4; ++i) c[mt][nt][i] = 0.f;

    uint4 pAh, pAl, pBh[NB], pBl[NB];

#define PREF(kc)                                                                  \
    do {                                                                          \
        pAh = GA_h[(bm + a_row) * 16 + (kc) * 4 + a_q];                           \
        pAl = GA_l[(bm + a_row) * 16 + (kc) * 4 + a_q];                           \
        _Pragma("unroll")                                                         \
        for (int j = 0; j < NB; ++j) {                                            \
            int idx = tid + j * 512;                                              \
            int kr = idx / (NC / 4), c4 = idx % (NC / 4);                         \
            pBh[j] = GW_h[wb4 + (((kc) * 16 + kr) * NC >> 2) + c4];               \
            pBl[j] = GW_l[wb4 + (((kc) * 16 + kr) * NC >> 2) + c4];               \
        }                                                                         \
    } while (0)

    PREF(0);

    for (int kc = 0; kc < 4; ++kc) {
        *reinterpret_cast<uint4*>(&As_h[a_row][a_q * 4]) = pAh;
        *reinterpret_cast<uint4*>(&As_l[a_row][a_q * 4]) = pAl;
#pragma unroll
        for (int j = 0; j < NB; ++j) {
            int idx = tid + j * 512;
            int kr = idx / (NC / 4), c4 = idx % (NC / 4);
            *reinterpret_cast<uint4*>(&Bs_h[kr][c4 * 4]) = pBh[j];
            *reinterpret_cast<uint4*>(&Bs_l[kr][c4 * 4]) = pBl[j];
        }
        __syncthreads();

        if (kc < 3) PREF(kc + 1);

#pragma unroll
        for (int st = 0; st < 2; ++st) {
            int kb2 = st * 8;
            uint32_t ah[2][4], al[2][4];
#pragma unroll
            for (int mt = 0; mt < 2; ++mt) {
                int rb = wm + mt * 16 + gi;
                ah[mt][0] = As_h[rb][kb2 + ti];
                ah[mt][1] = As_h[rb + 8][kb2 + ti];
                ah[mt][2] = As_h[rb][kb2 + ti + 4];
                ah[mt][3] = As_h[rb + 8][kb2 + ti + 4];
                al[mt][0] = As_l[rb][kb2 + ti];
                al[mt][1] = As_l[rb + 8][kb2 + ti];
                al[mt][2] = As_l[rb][kb2 + ti + 4];
                al[mt][3] = As_l[rb + 8][kb2 + ti + 4];
            }
#pragma unroll
            for (int nt = 0; nt < NT; ++nt) {
                int cb = wn + nt * 8 + gi;
                uint32_t bh[2], bl[2];
                bh[0] = Bs_h[kb2 + ti][cb];
                bh[1] = Bs_h[kb2 + ti + 4][cb];
                bl[0] = Bs_l[kb2 + ti][cb];
                bl[1] = Bs_l[kb2 + ti + 4][cb];
#pragma unroll
                for (int mt = 0; mt < 2; ++mt) {
                    mma16(c[mt][nt], ah[mt], bh);
                    mma16(c[mt][nt], al[mt], bh);
                    mma16(c[mt][nt], ah[mt], bl);
                }
            }
        }
        __syncthreads();
    }
#undef PREF

    // epilogue: self cols -> fp32 g_T; neighbor cols -> half2 g_Tn
#pragma unroll
    for (int mt = 0; mt < 2; ++mt) {
        int r0 = bm + wm + mt * 16 + gi;
        int r1 = r0 + 8;
#pragma unroll
        for (int nt = 0; nt < NT; ++nt) {
            int colg = wn + nt * 8 + ti * 2;
            if (colg < dsplit) {
                if (r0 < NN)
                    *reinterpret_cast<float2*>(g_T + r0 * dsplit + colg) =
                        make_float2(c[mt][nt][0], c[mt][nt][1]);
                if (r1 < NN)
                    *reinterpret_cast<float2*>(g_T + r1 * dsplit + colg) =
                        make_float2(c[mt][nt][2], c[mt][nt][3]);
            } else {
                int pc = (colg - dsplit) >> 1;
                if (r0 < NN) {
                    __half2 h2 = __floats2half2_rn(c[mt][nt][0], c[mt][nt][1]);
                    g_Tn[r0 * tn_str + pc] = *reinterpret_cast<uint32_t*>(&h2);
                }
                if (r1 < NN) {
                    __half2 h2 = __floats2half2_rn(c[mt][nt][2], c[mt][nt][3]);
                    g_Tn[r1 * tn_str + pc] = *reinterpret_cast<uint32_t*>(&h2);
                }
            }
        }
    }
}

// ---------------- finish ----------------
__global__ __launch_bounds__(256) void k_finish(const float* __restrict__ bias,
                                                float* __restrict__ outext, int mode) {
    int warp = threadIdx.x >> 5, lane = threadIdx.x & 31;
    int n = blockIdx.x * 8 + warp;
    if (n >= NN) return;
    int s0 = g_off[n], s1 = g_off[n + 1];
    float inv = 1.0f / (float)((s1 - s0) > 0 ? (s1 - s0) : 1);

    if (mode == 0) {
        float4 acc = make_float4(0.f, 0.f, 0.f, 0.f);
        float4 ac2 = make_float4(0.f, 0.f, 0.f, 0.f);
        int i = s0;
        for (; i + 2 <= s1; i += 2) {
            int sa = g_csr[i], sb = g_csr[i + 1];
            uint2 va = *reinterpret_cast<const uint2*>(g_Tn + sa * 64 + lane * 2);
            uint2 vb = *reinterpret_cast<const uint2*>(g_Tn + sb * 64 + lane * 2);
            float2 a0 = __half22float2(*reinterpret_cast<__half2*>(&va.x));
            float2 a1 = __half22float2(*reinterpret_cast<__half2*>(&va.y));
            float2 b0 = __half22float2(*reinterpret_cast<__half2*>(&vb.x));
            float2 b1 = __half22float2(*reinterpret_cast<__half2*>(&vb.y));
            acc.x += a0.x; acc.y += a0.y; acc.z += a1.x; acc.w += a1.y;
            ac2.x += b0.x; ac2.y += b0.y; ac2.z += b1.x; ac2.w += b1.y;
        }
        if (i < s1) {
            uint2 va = *reinterpret_cast<const uint2*>(g_Tn + g_csr[i] * 64 + lane * 2);
            float2 a0 = __half22float2(*reinterpret_cast<__half2*>(&va.x));
            float2 a1 = __half22float2(*reinterpret_cast<__half2*>(&va.y));
            acc.x += a0.x; acc.y += a0.y; acc.z += a1.x; acc.w += a1.y;
        }
        acc.x += ac2.x; acc.y += ac2.y; acc.z += ac2.z; acc.w += ac2.w;
        float4 p = *reinterpret_cast<const float4*>(g_T + n * 128 + lane * 4);
        float4 b = *reinterpret_cast<const float4*>(bias + lane * 4);
        float4 r;
        r.x = fmaxf(p.x + acc.x * inv + b.x, 0.f);
        r.y = fmaxf(p.y + acc.y * inv + b.y, 0.f);
        r.z = fmaxf(p.z + acc.z * inv + b.z, 0.f);
        r.w = fmaxf(p.w + acc.w * inv + b.w, 0.f);
        uint32_t h0, l0, h1, l1;
        split_pair(r.x, r.y, h0, l0);
        split_pair(r.z, r.w, h1, l1);
        int i0 = n * 64 + lane * 2;
        g_Ah[i0] = h0;     g_Al[i0] = l0;
        g_Ah[i0 + 1] = h1; g_Al[i0 + 1] = l1;
    } else {
        float2 acc = make_float2(0.f, 0.f);
        float2 ac2 = make_float2(0.f, 0.f);
        int i = s0;
        for (; i + 2 <= s1; i += 2) {
            uint32_t va = g_Tn[g_csr[i] * 32 + lane];
            uint32_t vb = g_Tn[g_csr[i + 1] * 32 + lane];
            float2 a = __half22float2(*reinterpret_cast<__half2*>(&va));
            float2 b = __half22float2(*reinterpret_cast<__half2*>(&vb));
            acc.x += a.x; acc.y += a.y;
            ac2.x += b.x; ac2.y += b.y;
        }
        if (i < s1) {
            uint32_t va = g_Tn[g_csr[i] * 32 + lane];
            float2 a = __half22float2(*reinterpret_cast<__half2*>(&va));
            acc.x += a.x; acc.y += a.y;
        }
        acc.x += ac2.x; acc.y += ac2.y;
        float2 p = *reinterpret_cast<const float2*>(g_T + n * 64 + lane * 2);
        float2 b = *reinterpret_cast<const float2*>(bias + lane * 2);
        float2 r;
        r.x = p.x + acc.x * inv + b.x;
        r.y = p.y + acc.y * inv + b.y;
        *reinterpret_cast<float2*>(outext + n * 64 + lane * 2) = r;
    }
}

// ---------------- launch ----------------
extern "C" void kernel_launch(void* const* d_in, const int* in_sizes, int n_in,
                              void* d_out, int out_size) {
    const float* x   = (const float*)d_in[0];
    const int*   src = (const int*)d_in[1];
    const int*   dst = (const int*)d_in[2];
    const float* Ws0 = (const float*)d_in[3];
    const float* Wn0 = (const float*)d_in[4];
    const float* b0  = (const float*)d_in[5];
    const float* Ws1 = (const float*)d_in[6];
    const float* Wn1 = (const float*)d_in[7];
    const float* b1  = (const float*)d_in[8];
    const float* Ws2 = (const float*)d_in[9];
    const float* Wn2 = (const float*)d_in[10];
    const float* b2  = (const float*)d_in[11];
    float* out = (float*)d_out;

    const int SM256 = 20480 + 2 * 16 * 264 * 4;   // 54272
    const int SM128 = 20480 + 2 * 16 * 136 * 4;   // 37888
    cudaFuncSetAttribute(k_gemm<256>, cudaFuncAttributeMaxDynamicSharedMemorySize, SM256);
    cudaFuncSetAttribute(k_gemm<128>, cudaFuncAttributeMaxDynamicSharedMemorySize, SM128);

    // fork: CSR build on side stream, concurrent with prep + layer-0 GEMM
    cudaStream_t s2;
    cudaStreamCreateWithFlags(&s2, cudaStreamNonBlocking);
    cudaEvent_t evStart, evCSR;
    cudaEventCreateWithFlags(&evStart, cudaEventDisableTiming);
    cudaEventCreateWithFlags(&evCSR, cudaEventDisableTiming);

    cudaEventRecord(evStart, 0);
    cudaStreamWaitEvent(s2, evStart, 0);
    k_zero<<<(NN + 255) / 256, 256, 0, s2>>>();
    k_hist<<<(EE + 255) / 256, 256, 0, s2>>>(dst);
    k_scanA<<<SB, 512, 0, s2>>>();
    k_scanC<<<SB, 512, 0, s2>>>();
    k_scatter<<<(EE + 255) / 256, 256, 0, s2>>>(src, dst);
    cudaEventRecord(evCSR, s2);

    // main stream: prep + layer-0 GEMM (independent of CSR)
    k_prep<<<(NN * 64 + 255) / 256, 256>>>(x, Ws0, Wn0, Ws1, Wn1, Ws2, Wn2);

    const int FB = (NN + 7) / 8;

    k_gemm<256><<<MT, 512, SM256>>>(0, 128, 64);
    cudaStreamWaitEvent(0, evCSR, 0);            // join before first gather
    k_finish<<<FB, 256>>>(b0, nullptr, 0);
    // Layer 1
    k_gemm<256><<<MT, 512, SM256>>>(16384, 128, 64);
    k_finish<<<FB, 256>>>(b1, nullptr, 0);
    // Layer 2
    k_gemm<128><<<MT, 512, SM128>>>(32768, 64, 32);
    k_finish<<<FB, 256>>>(b2, out, 2);
}